// round 1
// baseline (speedup 1.0000x reference)
#include <cuda_runtime.h>

#define NCH        30
#define CELLS_PER  49
#define COORDW     5.0f
#define NOOBJW     0.5f

// scratch for deterministic two-pass reduction (no cudaMalloc allowed)
__device__ float g_partials[8192];

__device__ __forceinline__ float warp_reduce(float v) {
    #pragma unroll
    for (int o = 16; o > 0; o >>= 1)
        v += __shfl_xor_sync(0xffffffffu, v, o);
    return v;
}

__device__ __forceinline__ void corners(float x, float y, float w, float h,
                                        float r, float c,
                                        float& x1, float& y1, float& x2, float& y2) {
    float cx = (x + c) / 7.0f;
    float cy = (y + r) / 7.0f;
    x1 = cx - w * 0.5f;
    y1 = cy - h * 0.5f;
    x2 = cx + w * 0.5f;
    y2 = cy + h * 0.5f;
}

__device__ __forceinline__ float iou(float ax1, float ay1, float ax2, float ay2,
                                     float bx1, float by1, float bx2, float by2) {
    float iw = fmaxf(fminf(ax2, bx2) - fmaxf(ax1, bx1), 0.0f);
    float ih = fmaxf(fminf(ay2, by2) - fmaxf(ay1, by1), 0.0f);
    float inter = iw * ih;
    float area_a = (ax2 - ax1) * (ay2 - ay1);
    float area_b = (bx2 - bx1) * (by2 - by1);
    float uni = area_a + area_b - inter;
    return (uni > 0.0f) ? inter / uni : 0.0f;
}

__global__ void yolo_loss_main(const float* __restrict__ data,
                               const float* __restrict__ labels,
                               int ncells) {
    int cell = blockIdx.x * blockDim.x + threadIdx.x;
    float loss = 0.0f;

    if (cell < ncells) {
        float d[NCH], l[NCH];
        const float2* dp = reinterpret_cast<const float2*>(data)   + (size_t)cell * 15;
        const float2* lp = reinterpret_cast<const float2*>(labels) + (size_t)cell * 15;
        #pragma unroll
        for (int i = 0; i < 15; i++) { float2 v = __ldg(dp + i); d[2*i] = v.x; d[2*i+1] = v.y; }
        #pragma unroll
        for (int i = 0; i < 15; i++) { float2 v = __ldg(lp + i); l[2*i] = v.x; l[2*i+1] = v.y; }

        int within = cell % CELLS_PER;
        float r = (float)(within / 7);
        float c = (float)(within % 7);

        float b1x1, b1y1, b1x2, b1y2;
        float b2x1, b2y1, b2x2, b2y2;
        float gx1,  gy1,  gx2,  gy2;
        corners(d[0], d[1], d[2], d[3], r, c, b1x1, b1y1, b1x2, b1y2);
        corners(d[5], d[6], d[7], d[8], r, c, b2x1, b2y1, b2x2, b2y2);
        corners(l[0], l[1], l[2], l[3], r, c, gx1,  gy1,  gx2,  gy2);

        float iou1 = iou(b1x1, b1y1, b1x2, b1y2, gx1, gy1, gx2, gy2);
        float iou2 = iou(b2x1, b2y1, b2x2, b2y2, gx1, gy1, gx2, gy2);
        bool resp1 = (iou1 >= iou2);

        float dx1 = d[0] - l[0], dy1 = d[1] - l[1];
        float dx2 = d[5] - l[5], dy2 = d[6] - l[6];
        float xy1 = dx1 * dx1 + dy1 * dy1;
        float xy2 = dx2 * dx2 + dy2 * dy2;

        float sw1 = sqrtf(d[2]) - sqrtf(l[2]);
        float sh1 = sqrtf(d[3]) - sqrtf(l[3]);
        float sw2 = sqrtf(d[7]) - sqrtf(l[7]);
        float sh2 = sqrtf(d[8]) - sqrtf(l[8]);
        float wh1 = sw1 * sw1 + sh1 * sh1;
        float wh2 = sw2 * sw2 + sh2 * sh2;

        float d4 = d[4], d9 = d[9];

        float co     = COORDW * (resp1 ? xy1 : xy2);
        float wh     = COORDW * (resp1 ? wh1 : wh2);
        float cdiff  = resp1 ? (d4 - iou1) : (d9 - iou2);
        float confi  = cdiff * cdiff;
        float nin    = NOOBJW * (resp1 ? d9 * d9 : d4 * d4);

        float cls = 0.0f;
        #pragma unroll
        for (int i = 10; i < 30; i++) {
            float e = d[i] - l[i];
            cls += e * e;
        }

        float m = (l[4] == 1.0f) ? 1.0f : 0.0f;
        float obj_loss   = m * (co + wh + confi + nin + cls);
        float noobj_loss = (1.0f - m) * NOOBJW * (d4 * d4 + d9 * d9);
        loss = obj_loss + noobj_loss;
    }

    // block-level deterministic reduction
    __shared__ float smem[32];
    float v = warp_reduce(loss);
    int lane = threadIdx.x & 31;
    int warp = threadIdx.x >> 5;
    if (lane == 0) smem[warp] = v;
    __syncthreads();
    int nwarps = (blockDim.x + 31) >> 5;
    if (warp == 0) {
        float w = (lane < nwarps) ? smem[lane] : 0.0f;
        w = warp_reduce(w);
        if (lane == 0) g_partials[blockIdx.x] = w;
    }
}

__global__ void yolo_loss_finalize(float* __restrict__ out, int nblocks, float invB) {
    float s = 0.0f;
    for (int i = threadIdx.x; i < nblocks; i += blockDim.x)
        s += g_partials[i];
    __shared__ float smem[32];
    float v = warp_reduce(s);
    int lane = threadIdx.x & 31;
    int warp = threadIdx.x >> 5;
    if (lane == 0) smem[warp] = v;
    __syncthreads();
    if (warp == 0) {
        float w = (lane < (int)(blockDim.x >> 5)) ? smem[lane] : 0.0f;
        w = warp_reduce(w);
        if (lane == 0) out[0] = w * invB;
    }
}

extern "C" void kernel_launch(void* const* d_in, const int* in_sizes, int n_in,
                              void* d_out, int out_size) {
    const float* data   = (const float*)d_in[0];
    const float* labels = (const float*)d_in[1];
    float* out = (float*)d_out;

    int total  = in_sizes[0];           // B*7*7*30
    int ncells = total / NCH;           // B*49
    int B      = ncells / CELLS_PER;

    const int TPB = 256;
    int nblocks = (ncells + TPB - 1) / TPB;   // 1568 for B=8192

    yolo_loss_main<<<nblocks, TPB>>>(data, labels, ncells);
    yolo_loss_finalize<<<1, 1024>>>(out, nblocks, 1.0f / (float)B);
}

// round 2
// speedup vs baseline: 1.0880x; 1.0880x over previous
#include <cuda_runtime.h>

#define NCH        30
#define COORDW     5.0f
#define NOOBJW     0.5f
#define TPB        128
#define CELLS_PB   128
#define FLOATS_PB  (CELLS_PB * NCH)     // 3840
#define F4_PB      (FLOATS_PB / 4)      // 960

__device__ float        g_partials[8192];
__device__ unsigned int g_count = 0;

__device__ __forceinline__ float warp_reduce(float v) {
    #pragma unroll
    for (int o = 16; o > 0; o >>= 1)
        v += __shfl_xor_sync(0xffffffffu, v, o);
    return v;
}

__device__ __forceinline__ void corners(float x, float y, float w, float h,
                                        float r, float c,
                                        float& x1, float& y1, float& x2, float& y2) {
    float cx = (x + c) * (1.0f / 7.0f);
    float cy = (y + r) * (1.0f / 7.0f);
    x1 = cx - w * 0.5f;
    y1 = cy - h * 0.5f;
    x2 = cx + w * 0.5f;
    y2 = cy + h * 0.5f;
}

__device__ __forceinline__ float iou(float ax1, float ay1, float ax2, float ay2,
                                     float bx1, float by1, float bx2, float by2) {
    float iw = fmaxf(fminf(ax2, bx2) - fmaxf(ax1, bx1), 0.0f);
    float ih = fmaxf(fminf(ay2, by2) - fmaxf(ay1, by1), 0.0f);
    float inter = iw * ih;
    float area_a = (ax2 - ax1) * (ay2 - ay1);
    float area_b = (bx2 - bx1) * (by2 - by1);
    float uni = area_a + area_b - inter;
    return (uni > 0.0f) ? inter / uni : 0.0f;
}

__device__ __forceinline__ float cell_loss(const float* __restrict__ d,
                                           const float* __restrict__ l,
                                           float r, float c) {
    float b1x1, b1y1, b1x2, b1y2;
    float b2x1, b2y1, b2x2, b2y2;
    float gx1,  gy1,  gx2,  gy2;
    corners(d[0], d[1], d[2], d[3], r, c, b1x1, b1y1, b1x2, b1y2);
    corners(d[5], d[6], d[7], d[8], r, c, b2x1, b2y1, b2x2, b2y2);
    corners(l[0], l[1], l[2], l[3], r, c, gx1,  gy1,  gx2,  gy2);

    float iou1 = iou(b1x1, b1y1, b1x2, b1y2, gx1, gy1, gx2, gy2);
    float iou2 = iou(b2x1, b2y1, b2x2, b2y2, gx1, gy1, gx2, gy2);
    bool resp1 = (iou1 >= iou2);

    float dx1 = d[0] - l[0], dy1 = d[1] - l[1];
    float dx2 = d[5] - l[5], dy2 = d[6] - l[6];
    float xy1 = dx1 * dx1 + dy1 * dy1;
    float xy2 = dx2 * dx2 + dy2 * dy2;

    float sw1 = sqrtf(d[2]) - sqrtf(l[2]);
    float sh1 = sqrtf(d[3]) - sqrtf(l[3]);
    float sw2 = sqrtf(d[7]) - sqrtf(l[7]);
    float sh2 = sqrtf(d[8]) - sqrtf(l[8]);
    float wh1 = sw1 * sw1 + sh1 * sh1;
    float wh2 = sw2 * sw2 + sh2 * sh2;

    float d4 = d[4], d9 = d[9];

    float co    = COORDW * (resp1 ? xy1 : xy2);
    float wh    = COORDW * (resp1 ? wh1 : wh2);
    float cdiff = resp1 ? (d4 - iou1) : (d9 - iou2);
    float confi = cdiff * cdiff;
    float nin   = NOOBJW * (resp1 ? d9 * d9 : d4 * d4);

    float cls = 0.0f;
    #pragma unroll
    for (int i = 10; i < 30; i++) {
        float e = d[i] - l[i];
        cls += e * e;
    }

    float m = (l[4] == 1.0f) ? 1.0f : 0.0f;
    float obj_loss   = m * (co + wh + confi + nin + cls);
    float noobj_loss = (1.0f - m) * NOOBJW * (d4 * d4 + d9 * d9);
    return obj_loss + noobj_loss;
}

__global__ void __launch_bounds__(TPB)
yolo_loss_fused(const float* __restrict__ data,
                const float* __restrict__ labels,
                float* __restrict__ out,
                int ncells, float invB, int nblocks) {
    __shared__ float sd[FLOATS_PB];
    __shared__ float sl[FLOATS_PB];
    __shared__ float sred[TPB / 32];
    __shared__ bool  s_last;

    const int tid = threadIdx.x;
    const int base_cell = blockIdx.x * CELLS_PB;
    const int cb = min(CELLS_PB, ncells - base_cell);

    if (cb == CELLS_PB) {
        // fully coalesced float4 staging (streaming: no reuse)
        const float4* dsrc = reinterpret_cast<const float4*>(data)   + (size_t)blockIdx.x * F4_PB;
        const float4* lsrc = reinterpret_cast<const float4*>(labels) + (size_t)blockIdx.x * F4_PB;
        float4* sd4 = reinterpret_cast<float4*>(sd);
        float4* sl4 = reinterpret_cast<float4*>(sl);
        #pragma unroll
        for (int i = 0; i < 8; i++) {
            int idx = i * TPB + tid;
            if (idx < F4_PB) {
                sd4[idx] = __ldcs(dsrc + idx);
                sl4[idx] = __ldcs(lsrc + idx);
            }
        }
    } else {
        // tail block: scalar, guarded
        for (int i = tid; i < cb * NCH; i += TPB) {
            sd[i] = data[(size_t)base_cell * NCH + i];
            sl[i] = labels[(size_t)base_cell * NCH + i];
        }
    }
    __syncthreads();

    float loss = 0.0f;
    if (tid < cb) {
        int cell = base_cell + tid;
        int within = cell % 49;
        float r = (float)(within / 7);
        float c = (float)(within % 7);
        loss = cell_loss(sd + tid * NCH, sl + tid * NCH, r, c);
    }

    // deterministic block reduction (4 warps)
    float v = warp_reduce(loss);
    int lane = tid & 31;
    int warp = tid >> 5;
    if (lane == 0) sred[warp] = v;
    __syncthreads();
    if (tid == 0) {
        float s = sred[0] + sred[1] + sred[2] + sred[3];
        g_partials[blockIdx.x] = s;
        __threadfence();
        unsigned int t = atomicAdd(&g_count, 1u);
        s_last = (t == (unsigned int)(nblocks - 1));
    }
    __syncthreads();

    if (s_last) {
        // last block: deterministic fixed-order sum of partials
        float s = 0.0f;
        for (int i = tid; i < nblocks; i += TPB)
            s += g_partials[i];
        float w = warp_reduce(s);
        if (lane == 0) sred[warp] = w;
        __syncthreads();
        if (tid == 0) {
            float tot = sred[0] + sred[1] + sred[2] + sred[3];
            out[0] = tot * invB;
            g_count = 0;   // reset for next graph replay
        }
    }
}

extern "C" void kernel_launch(void* const* d_in, const int* in_sizes, int n_in,
                              void* d_out, int out_size) {
    const float* data   = (const float*)d_in[0];
    const float* labels = (const float*)d_in[1];
    float* out = (float*)d_out;

    int total  = in_sizes[0];           // B*7*7*30
    int ncells = total / NCH;           // B*49
    int B      = ncells / 49;

    int nblocks = (ncells + CELLS_PB - 1) / CELLS_PB;   // 3136 for B=8192

    yolo_loss_fused<<<nblocks, TPB>>>(data, labels, out, ncells, 1.0f / (float)B, nblocks);
}

// round 3
// speedup vs baseline: 1.5009x; 1.3795x over previous
#include <cuda_runtime.h>

#define NCH        30
#define COORDW     5.0f
#define NOOBJW     0.5f
#define TPB        128
#define CELLS_PB   128
#define TILE_FLOATS (CELLS_PB * NCH)          // 3840 per array
#define TILE_F4     (TILE_FLOATS / 4)         // 960
#define STAGE_FLOATS (2 * TILE_FLOATS)        // sd + sl = 7680
#define SMEM_FLOATS  (2 * STAGE_FLOATS)       // 2 stages = 15360
#define SMEM_BYTES   (SMEM_FLOATS * 4)        // 61440
#define MAXGRID    1024

__device__ float        g_partials[MAXGRID];
__device__ unsigned int g_count = 0;

__device__ __forceinline__ void cp16(float4* smem_dst, const float4* gmem_src) {
    unsigned int s = (unsigned int)__cvta_generic_to_shared(smem_dst);
    asm volatile("cp.async.cg.shared.global [%0], [%1], 16;\n" :: "r"(s), "l"(gmem_src));
}
__device__ __forceinline__ void cp_commit() {
    asm volatile("cp.async.commit_group;\n");
}
__device__ __forceinline__ void cp_wait1() {
    asm volatile("cp.async.wait_group 1;\n");
}
__device__ __forceinline__ void cp_wait0() {
    asm volatile("cp.async.wait_group 0;\n");
}

__device__ __forceinline__ float warp_reduce(float v) {
    #pragma unroll
    for (int o = 16; o > 0; o >>= 1)
        v += __shfl_xor_sync(0xffffffffu, v, o);
    return v;
}

__device__ __forceinline__ void corners(float x, float y, float w, float h,
                                        float r, float c,
                                        float& x1, float& y1, float& x2, float& y2) {
    float cx = (x + c) * (1.0f / 7.0f);
    float cy = (y + r) * (1.0f / 7.0f);
    x1 = cx - w * 0.5f;
    y1 = cy - h * 0.5f;
    x2 = cx + w * 0.5f;
    y2 = cy + h * 0.5f;
}

__device__ __forceinline__ float iou(float ax1, float ay1, float ax2, float ay2,
                                     float bx1, float by1, float bx2, float by2) {
    float iw = fmaxf(fminf(ax2, bx2) - fmaxf(ax1, bx1), 0.0f);
    float ih = fmaxf(fminf(ay2, by2) - fmaxf(ay1, by1), 0.0f);
    float inter = iw * ih;
    float area_a = (ax2 - ax1) * (ay2 - ay1);
    float area_b = (bx2 - bx1) * (by2 - by1);
    float uni = area_a + area_b - inter;
    return (uni > 0.0f) ? inter / uni : 0.0f;
}

__device__ __forceinline__ float cell_loss(const float* __restrict__ d,
                                           const float* __restrict__ l,
                                           float r, float c) {
    float b1x1, b1y1, b1x2, b1y2;
    float b2x1, b2y1, b2x2, b2y2;
    float gx1,  gy1,  gx2,  gy2;
    corners(d[0], d[1], d[2], d[3], r, c, b1x1, b1y1, b1x2, b1y2);
    corners(d[5], d[6], d[7], d[8], r, c, b2x1, b2y1, b2x2, b2y2);
    corners(l[0], l[1], l[2], l[3], r, c, gx1,  gy1,  gx2,  gy2);

    float iou1 = iou(b1x1, b1y1, b1x2, b1y2, gx1, gy1, gx2, gy2);
    float iou2 = iou(b2x1, b2y1, b2x2, b2y2, gx1, gy1, gx2, gy2);
    bool resp1 = (iou1 >= iou2);

    float dx1 = d[0] - l[0], dy1 = d[1] - l[1];
    float dx2 = d[5] - l[5], dy2 = d[6] - l[6];
    float xy1 = dx1 * dx1 + dy1 * dy1;
    float xy2 = dx2 * dx2 + dy2 * dy2;

    float sw1 = sqrtf(d[2]) - sqrtf(l[2]);
    float sh1 = sqrtf(d[3]) - sqrtf(l[3]);
    float sw2 = sqrtf(d[7]) - sqrtf(l[7]);
    float sh2 = sqrtf(d[8]) - sqrtf(l[8]);
    float wh1 = sw1 * sw1 + sh1 * sh1;
    float wh2 = sw2 * sw2 + sh2 * sh2;

    float d4 = d[4], d9 = d[9];

    float co    = COORDW * (resp1 ? xy1 : xy2);
    float wh    = COORDW * (resp1 ? wh1 : wh2);
    float cdiff = resp1 ? (d4 - iou1) : (d9 - iou2);
    float confi = cdiff * cdiff;
    float nin   = NOOBJW * (resp1 ? d9 * d9 : d4 * d4);

    float cls = 0.0f;
    #pragma unroll
    for (int i = 10; i < 30; i++) {
        float e = d[i] - l[i];
        cls += e * e;
    }

    float m = (l[4] == 1.0f) ? 1.0f : 0.0f;
    float obj_loss   = m * (co + wh + confi + nin + cls);
    float noobj_loss = (1.0f - m) * NOOBJW * (d4 * d4 + d9 * d9);
    return obj_loss + noobj_loss;
}

// stage one full tile into smem buffers via cp.async (no commit here)
__device__ __forceinline__ void stage_tile(const float* __restrict__ data,
                                           const float* __restrict__ labels,
                                           int tile, float* sbuf, int tid) {
    const float4* d4 = reinterpret_cast<const float4*>(data)   + (size_t)tile * TILE_F4;
    const float4* l4 = reinterpret_cast<const float4*>(labels) + (size_t)tile * TILE_F4;
    float4* sd4 = reinterpret_cast<float4*>(sbuf);
    float4* sl4 = reinterpret_cast<float4*>(sbuf + TILE_FLOATS);
    #pragma unroll
    for (int i = 0; i < 8; i++) {
        int idx = i * TPB + tid;
        if (idx < TILE_F4) {
            cp16(sd4 + idx, d4 + idx);
            cp16(sl4 + idx, l4 + idx);
        }
    }
}

__global__ void __launch_bounds__(TPB)
yolo_loss_pipe(const float* __restrict__ data,
               const float* __restrict__ labels,
               float* __restrict__ out,
               int ncells, float invB, int ntiles) {
    extern __shared__ float smem[];   // [2][STAGE_FLOATS]
    __shared__ float sred[TPB / 32];
    __shared__ bool  s_last;

    const int tid = threadIdx.x;
    const int lane = tid & 31;
    const int warp = tid >> 5;
    const int gstride = gridDim.x;

    float acc = 0.0f;

    int tile = blockIdx.x;
    bool first_full = (tile < ntiles) && (tile * CELLS_PB + CELLS_PB <= ncells);
    if (first_full)
        stage_tile(data, labels, tile, smem, tid);
    cp_commit();

    int it = 0;
    while (tile < ntiles) {
        int next = tile + gstride;
        bool next_full = (next < ntiles) && (next * CELLS_PB + CELLS_PB <= ncells);
        bool cur_full  = (tile * CELLS_PB + CELLS_PB <= ncells);

        if (next_full)
            stage_tile(data, labels, next, smem + ((it + 1) & 1) * STAGE_FLOATS, tid);
        cp_commit();

        cp_wait1();          // current tile's copy complete
        __syncthreads();

        if (cur_full) {
            const float* sd = smem + (it & 1) * STAGE_FLOATS;
            const float* sl = sd + TILE_FLOATS;
            int cell = tile * CELLS_PB + tid;
            int within = cell % 49;
            float r = (float)(within / 7);
            float c = (float)(within % 7);
            acc += cell_loss(sd + tid * NCH, sl + tid * NCH, r, c);
        } else {
            // partial tail tile: direct global loads (rare/one-off)
            int cell = tile * CELLS_PB + tid;
            if (cell < ncells) {
                float d[NCH], l[NCH];
                const float2* dp = reinterpret_cast<const float2*>(data)   + (size_t)cell * 15;
                const float2* lp = reinterpret_cast<const float2*>(labels) + (size_t)cell * 15;
                #pragma unroll
                for (int i = 0; i < 15; i++) { float2 v = dp[i]; d[2*i] = v.x; d[2*i+1] = v.y; }
                #pragma unroll
                for (int i = 0; i < 15; i++) { float2 v = lp[i]; l[2*i] = v.x; l[2*i+1] = v.y; }
                int within = cell % 49;
                float r = (float)(within / 7);
                float c = (float)(within % 7);
                acc += cell_loss(d, l, r, c);
            }
        }
        __syncthreads();     // buffer (it&1) free for reuse
        tile = next;
        it++;
    }
    cp_wait0();

    // deterministic block reduction
    float v = warp_reduce(acc);
    if (lane == 0) sred[warp] = v;
    __syncthreads();
    if (tid == 0) {
        float s = sred[0] + sred[1] + sred[2] + sred[3];
        g_partials[blockIdx.x] = s;
        __threadfence();
        unsigned int t = atomicAdd(&g_count, 1u);
        s_last = (t == (unsigned int)(gridDim.x - 1));
    }
    __syncthreads();

    if (s_last) {
        float s = 0.0f;
        for (int i = tid; i < (int)gridDim.x; i += TPB)
            s += g_partials[i];
        float w = warp_reduce(s);
        if (lane == 0) sred[warp] = w;
        __syncthreads();
        if (tid == 0) {
            float tot = sred[0] + sred[1] + sred[2] + sred[3];
            out[0] = tot * invB;
            g_count = 0;   // reset for next graph replay
        }
    }
}

extern "C" void kernel_launch(void* const* d_in, const int* in_sizes, int n_in,
                              void* d_out, int out_size) {
    const float* data   = (const float*)d_in[0];
    const float* labels = (const float*)d_in[1];
    float* out = (float*)d_out;

    int total  = in_sizes[0];           // B*7*7*30
    int ncells = total / NCH;           // B*49
    int B      = ncells / 49;

    int ntiles = (ncells + CELLS_PB - 1) / CELLS_PB;    // 3136 for B=8192
    int grid   = 444;                                    // 148 SM x 3 blocks
    if (grid > ntiles) grid = ntiles;
    if (grid > MAXGRID) grid = MAXGRID;

    static bool attr_set = false;
    if (!attr_set) {
        cudaFuncSetAttribute(yolo_loss_pipe,
                             cudaFuncAttributeMaxDynamicSharedMemorySize, SMEM_BYTES);
        attr_set = true;
    }

    yolo_loss_pipe<<<grid, TPB, SMEM_BYTES>>>(data, labels, out,
                                              ncells, 1.0f / (float)B, ntiles);
}